// round 16
// baseline (speedup 1.0000x reference)
#include <cuda_runtime.h>
#include <cuda_bf16.h>
#include <cstdint>
#include <cstddef>

#define Bsz 64
#define Tt  2048
#define H1c 256
#define H2c 128
#define Oc  10
#define EPSf 1e-5f

// ---------------- static device scratch (no cudaMalloc allowed) -------------
__device__ float g_GX1[(size_t)Bsz * Tt * 3 * H1c];   // [B,T,768]
__device__ float g_H1 [(size_t)Bsz * Tt * H1c];       // [B,T,256]
__device__ float g_GX2[(size_t)Bsz * Tt * 3 * H2c];   // [B,T,384]
__device__ float g_H2 [(size_t)Bsz * Tt * H2c];       // [B,T,128]
__device__ float g_W2eff[3 * H2c * H1c];
__device__ float g_b2eff[3 * H2c];

__device__ __forceinline__ float sigm_(float x) {
    return __fdividef(1.f, 1.f + __expf(-x));
}
__device__ __forceinline__ float tanh_(float x) {
    return 1.f - __fdividef(2.f, __expf(2.f * x) + 1.f);
}

// packed fp32x2 FMA
__device__ __forceinline__ unsigned long long
fma2_(unsigned long long a, unsigned long long b, unsigned long long c) {
    unsigned long long d;
    asm("fma.rn.f32x2 %0, %1, %2, %3;" : "=l"(d) : "l"(a), "l"(b), "l"(c));
    return d;
}
__device__ __forceinline__ float2 unpack2_(unsigned long long v) {
    unsigned int lo, hi;
    asm("mov.b64 {%0, %1}, %2;" : "=r"(lo), "=r"(hi) : "l"(v));
    return make_float2(__uint_as_float(lo), __uint_as_float(hi));
}
__device__ __forceinline__ unsigned long long pack2_(float x, float y) {
    unsigned long long r;
    asm("mov.b64 %0, {%1, %2};" : "=l"(r) : "f"(x), "f"(y));
    return r;
}

// mbarrier helpers
__device__ __forceinline__ uint32_t smem_u32_(const void* p) {
    return (uint32_t)__cvta_generic_to_shared(p);
}
__device__ __forceinline__ void mb_init_(uint32_t mb, uint32_t cnt) {
    asm volatile("mbarrier.init.shared.b64 [%0], %1;" :: "r"(mb), "r"(cnt) : "memory");
}
__device__ __forceinline__ void mb_expect_(uint32_t mb, uint32_t tx) {
    asm volatile("mbarrier.arrive.expect_tx.shared.b64 _, [%0], %1;"
                 :: "r"(mb), "r"(tx) : "memory");
}
__device__ __forceinline__ void mb_wait_(uint32_t mb, uint32_t parity) {
    uint32_t done;
    do {
        asm volatile(
            "{\n\t.reg .pred p;\n\t"
            "mbarrier.try_wait.parity.acquire.cluster.shared::cta.b64 p, [%1], %2, 0x989680;\n\t"
            "selp.b32 %0, 1, 0, p;\n\t}"
            : "=r"(done) : "r"(mb), "r"(parity) : "memory");
    } while (!done);
}
__device__ __forceinline__ uint32_t mapa_(uint32_t addr, uint32_t rank) {
    uint32_t r;
    asm volatile("mapa.shared::cluster.u32 %0, %1, %2;" : "=r"(r) : "r"(addr), "r"(rank));
    return r;
}
__device__ __forceinline__ void st_async_f32_(uint32_t daddr, float v, uint32_t dmbar) {
    asm volatile("st.async.shared::cluster.mbarrier::complete_tx::bytes.b32 [%0], %1, [%2];"
                 :: "r"(daddr), "r"(__float_as_uint(v)), "r"(dmbar) : "memory");
}
#define CLUSTER_SYNC_() do { \
    asm volatile("barrier.cluster.arrive.aligned;" ::: "memory"); \
    asm volatile("barrier.cluster.wait.aligned;"   ::: "memory"); \
} while (0)

// ---------------- prep: fold eval-BN1 into layer-2 input weights ------------
__global__ void __launch_bounds__(256)
prep_kernel(const float* __restrict__ Wih2, const float* __restrict__ bih2,
            const float* __restrict__ g1, const float* __restrict__ be1,
            const float* __restrict__ m1, const float* __restrict__ v1)
{
    __shared__ float red[256];
    const int j = blockIdx.x;          // 0..383
    const int k = threadIdx.x;         // 0..255
    float s  = g1[k] * rsqrtf(v1[k] + EPSf);
    float tb = be1[k] - m1[k] * s;
    float w  = Wih2[j * 256 + k];
    g_W2eff[j * 256 + k] = w * s;
    red[k] = w * tb;
    __syncthreads();
    for (int s2 = 128; s2 > 0; s2 >>= 1) {
        if (k < s2) red[k] += red[k + s2];
        __syncthreads();
    }
    if (k == 0) g_b2eff[j] = bih2[j] + red[0];
}

// ---------------- GEMM: C[M,N] = A[M,K] @ B[N,K]^T + bias[N] ---------------
__global__ void __launch_bounds__(256)
gemm_bias_kernel(const float* __restrict__ A, const float* __restrict__ B,
                 const float* __restrict__ bias, float* __restrict__ C,
                 int N, int K)
{
    __shared__ __align__(16) float As[16][128];
    __shared__ __align__(16) float Bs[16][64];
    const int tid = threadIdx.x;
    const int bn = blockIdx.x * 64;
    const int bm = blockIdx.y * 128;
    const int tx = tid & 15;
    const int ty = tid >> 4;
    unsigned long long acc2[4][4];
#pragma unroll
    for (int i = 0; i < 4; i++)
#pragma unroll
        for (int j = 0; j < 4; j++) acc2[i][j] = 0ull;

    for (int k0 = 0; k0 < K; k0 += 16) {
#pragma unroll
        for (int i = 0; i < 2; i++) {
            int idx = (tid + i * 256) * 4;
            int r = idx >> 4, c = idx & 15;
            float4 v = *reinterpret_cast<const float4*>(A + (size_t)(bm + r) * K + k0 + c);
            As[c][r] = v.x; As[c + 1][r] = v.y; As[c + 2][r] = v.z; As[c + 3][r] = v.w;
        }
        {
            int idx = tid * 4;
            int r = idx >> 4, c = idx & 15;
            float4 v = *reinterpret_cast<const float4*>(B + (size_t)(bn + r) * K + k0 + c);
            Bs[c][r] = v.x; Bs[c + 1][r] = v.y; Bs[c + 2][r] = v.z; Bs[c + 3][r] = v.w;
        }
        __syncthreads();
#pragma unroll
        for (int kk = 0; kk < 16; kk++) {
            const unsigned long long* ar =
                reinterpret_cast<const unsigned long long*>(&As[kk][ty * 8]);
            unsigned long long a0 = ar[0], a1 = ar[1], a2 = ar[2], a3 = ar[3];
            float4 bf = *reinterpret_cast<const float4*>(&Bs[kk][tx * 4]);
            unsigned long long b0 = pack2_(bf.x, bf.x);
            unsigned long long b1 = pack2_(bf.y, bf.y);
            unsigned long long b2 = pack2_(bf.z, bf.z);
            unsigned long long b3 = pack2_(bf.w, bf.w);
            acc2[0][0] = fma2_(a0, b0, acc2[0][0]); acc2[0][1] = fma2_(a0, b1, acc2[0][1]);
            acc2[0][2] = fma2_(a0, b2, acc2[0][2]); acc2[0][3] = fma2_(a0, b3, acc2[0][3]);
            acc2[1][0] = fma2_(a1, b0, acc2[1][0]); acc2[1][1] = fma2_(a1, b1, acc2[1][1]);
            acc2[1][2] = fma2_(a1, b2, acc2[1][2]); acc2[1][3] = fma2_(a1, b3, acc2[1][3]);
            acc2[2][0] = fma2_(a2, b0, acc2[2][0]); acc2[2][1] = fma2_(a2, b1, acc2[2][1]);
            acc2[2][2] = fma2_(a2, b2, acc2[2][2]); acc2[2][3] = fma2_(a2, b3, acc2[2][3]);
            acc2[3][0] = fma2_(a3, b0, acc2[3][0]); acc2[3][1] = fma2_(a3, b1, acc2[3][1]);
            acc2[3][2] = fma2_(a3, b2, acc2[3][2]); acc2[3][3] = fma2_(a3, b3, acc2[3][3]);
        }
        __syncthreads();
    }
    const int n = bn + tx * 4;
    float4 bv = *reinterpret_cast<const float4*>(bias + n);
#pragma unroll
    for (int i = 0; i < 4; i++) {
        float2 c0 = unpack2_(acc2[i][0]);
        float2 c1 = unpack2_(acc2[i][1]);
        float2 c2 = unpack2_(acc2[i][2]);
        float2 c3 = unpack2_(acc2[i][3]);
        int m = bm + ty * 8 + 2 * i;
        float4 o0, o1;
        o0.x = c0.x + bv.x; o0.y = c1.x + bv.y; o0.z = c2.x + bv.z; o0.w = c3.x + bv.w;
        o1.x = c0.y + bv.x; o1.y = c1.y + bv.y; o1.z = c2.y + bv.z; o1.w = c3.y + bv.w;
        *reinterpret_cast<float4*>(C + (size_t)m * N + n)       = o0;
        *reinterpret_cast<float4*>(C + (size_t)(m + 1) * N + n) = o1;
    }
}

// ---------------- GRU layer 1: 4-CTA cluster, batch-staggered pipeline ------
// Two independent batch recurrences per cluster, processed in alternating
// phases so each batch's DSMEM h-exchange latency is hidden behind the other
// batch's dot+combine. hbf layout: [bb][parity][2 khalf x 132] floats.
// mbarriers: [bb][parity] (4).
__global__ void __cluster_dims__(4, 1, 1) __launch_bounds__(384, 1)
gru1_kernel(const float* __restrict__ Whh, const float* __restrict__ bhh)
{
    __shared__ __align__(16) float hbf[1056];
    __shared__ float gsh[384];            // [bb][192]
    __shared__ __align__(8) unsigned long long mbs[4];

    const int tid  = threadIdx.x;        // 0..383
    const int rank = blockIdx.x & 3;
    const int b0   = (blockIdx.x >> 2) * 2;
    const int g    = tid >> 1;           // local gate row 0..191
    const int q    = tid & 1;            // k half
    const int grow = ((g >> 6) << 8) + rank * 64 + (g & 63);

    unsigned long long w[64];
    {
        const unsigned long long* wp = reinterpret_cast<const unsigned long long*>(
            Whh + (size_t)grow * 256 + q * 128);
#pragma unroll
        for (int i = 0; i < 64; i++) w[i] = wp[i];
    }
    // combine-role constants + bias registers (tid<128: bb=tid>>6, jl=tid&63)
    const int jl  = tid & 63;
    const int bbc = (tid >> 6) & 1;
    const int j   = rank * 64 + jl;
    float br = 0.f, bz = 0.f, bn_ = 0.f;
    if (tid < 128) {
        br  = bhh[j];
        bz  = bhh[256 + j];
        bn_ = bhh[512 + j];
    }
    for (int i = tid; i < 1056; i += 384) hbf[i] = 0.f;

    const uint32_t mb_base = smem_u32_(mbs);
    if (tid == 0) {
#pragma unroll
        for (int i = 0; i < 4; i++) mb_init_(mb_base + i * 8, 1);
        mb_expect_(mb_base + 8,  1024);   // b0, parity1 buffer: h(0)
        mb_expect_(mb_base + 0,  1024);   // b0, parity0 buffer: h(1)
        mb_expect_(mb_base + 24, 1024);   // b1, parity1
        mb_expect_(mb_base + 16, 1024);   // b1, parity0
    }
    __syncthreads();
    CLUSTER_SYNC_();

    const int slot = (j >> 7) * 132 + (j & 127);
    const uint32_t hbase  = smem_u32_(hbf);
    const uint32_t myslot = hbase + (uint32_t)((bbc * 528 + slot) * 4);

    int p00 = 0, p01 = 0, p10 = 0, p11 = 0;

#pragma unroll 1
    for (int t = 0; t < Tt; t++) {
        const int p = t & 1;

        // -------- phase A: batch 0 --------
        if (t) {
            if (p) { mb_wait_(mb_base + 8, p01); p01 ^= 1; }
            else   { mb_wait_(mb_base + 0, p00); p00 ^= 1; }
        }
        if (tid == 0 && t >= 1 && t + 2 < Tt)
            mb_expect_(mb_base + (uint32_t)(p * 8), 1024);

        // prefetch gx for both batches (each combine thread its own)
        float gxr = 0.f, gxz = 0.f, gxn = 0.f;
        if (tid < 128) {
            const float* gxp = g_GX1 + ((size_t)(b0 + bbc) * Tt + t) * 768 + j;
            gxr = __ldcs(gxp);
            gxz = __ldcs(gxp + 256);
            gxn = __ldcs(gxp + 512);
        }

        {
            const unsigned long long* hb =
                reinterpret_cast<const unsigned long long*>(hbf) + p * 132 + q * 66;
            unsigned long long a = 0ull;
#pragma unroll
            for (int i = 0; i < 64; i++) a = fma2_(w[i], hb[i], a);
            float2 f = unpack2_(a);
            float d = f.x + f.y;
            d += __shfl_xor_sync(0xFFFFFFFFu, d, 1);
            if (q == 0) gsh[g] = d;
        }
        __syncthreads();

        if (tid < 64) {   // combine batch 0
            float r = sigm_(gxr + gsh[jl]       + br);
            float z = sigm_(gxz + gsh[64 + jl]  + bz);
            float n = tanh_(gxn + r * (gsh[128 + jl] + bn_));
            float hold = hbf[p * 264 + slot];
            float hnew = (1.f - z) * n + z * hold;
            if (t + 1 < Tt) {
                uint32_t loc = myslot + (uint32_t)(((p ^ 1) * 264) * 4);
                uint32_t mbb = mb_base + (uint32_t)((p ^ 1) * 8);
#pragma unroll
                for (int c = 0; c < 4; c++)
                    st_async_f32_(mapa_(loc, (uint32_t)c), hnew,
                                  mapa_(mbb, (uint32_t)c));
            }
            __stcs(&g_H1[((size_t)b0 * Tt + t) * 256 + j], hnew);
        }

        // -------- phase B: batch 1 --------
        if (t) {
            if (p) { mb_wait_(mb_base + 24, p11); p11 ^= 1; }
            else   { mb_wait_(mb_base + 16, p10); p10 ^= 1; }
        }
        if (tid == 0 && t >= 1 && t + 2 < Tt)
            mb_expect_(mb_base + (uint32_t)(16 + p * 8), 1024);

        {
            const unsigned long long* hb =
                reinterpret_cast<const unsigned long long*>(hbf) + 264 + p * 132 + q * 66;
            unsigned long long a = 0ull;
#pragma unroll
            for (int i = 0; i < 64; i++) a = fma2_(w[i], hb[i], a);
            float2 f = unpack2_(a);
            float d = f.x + f.y;
            d += __shfl_xor_sync(0xFFFFFFFFu, d, 1);
            if (q == 0) gsh[192 + g] = d;
        }
        __syncthreads();

        if (tid >= 64 && tid < 128) {   // combine batch 1
            float r = sigm_(gxr + gsh[192 + jl]       + br);
            float z = sigm_(gxz + gsh[256 + jl]       + bz);
            float n = tanh_(gxn + r * (gsh[320 + jl] + bn_));
            float hold = hbf[528 + p * 264 + slot];
            float hnew = (1.f - z) * n + z * hold;
            if (t + 1 < Tt) {
                uint32_t loc = myslot + (uint32_t)(((p ^ 1) * 264) * 4);
                uint32_t mbb = mb_base + (uint32_t)(16 + (p ^ 1) * 8);
#pragma unroll
                for (int c = 0; c < 4; c++)
                    st_async_f32_(mapa_(loc, (uint32_t)c), hnew,
                                  mapa_(mbb, (uint32_t)c));
            }
            __stcs(&g_H1[((size_t)(b0 + 1) * Tt + t) * 256 + j], hnew);
        }
    }
    CLUSTER_SYNC_();
}

// ---------------- GRU layer 2: 1 CTA / batch, inline combine ---------------
// 256 threads: thread (j=tid>>1, q=tid&1) holds all 3 gate rows for hidden
// unit j over k-half q (96 u64 weight regs). One __syncthreads per step.
__global__ void __launch_bounds__(256, 1)
gru2_kernel(const float* __restrict__ Whh, const float* __restrict__ bhh)
{
    __shared__ __align__(16) float hsh[2][128];

    const int tid = threadIdx.x;   // 0..255
    const int b   = blockIdx.x;
    const int j   = tid >> 1;
    const int q   = tid & 1;

    unsigned long long wr[32], wz[32], wn[32];
    {
        const unsigned long long* pr = reinterpret_cast<const unsigned long long*>(
            Whh + (size_t)j * 128 + q * 64);
        const unsigned long long* pz = reinterpret_cast<const unsigned long long*>(
            Whh + (size_t)(128 + j) * 128 + q * 64);
        const unsigned long long* pn = reinterpret_cast<const unsigned long long*>(
            Whh + (size_t)(256 + j) * 128 + q * 64);
#pragma unroll
        for (int i = 0; i < 32; i++) { wr[i] = pr[i]; wz[i] = pz[i]; wn[i] = pn[i]; }
    }
    float br = 0.f, bz = 0.f, bn_ = 0.f;
    if (q == 0) { br = bhh[j]; bz = bhh[128 + j]; bn_ = bhh[256 + j]; }
    if (tid < 128) { hsh[0][tid] = 0.f; hsh[1][tid] = 0.f; }
    __syncthreads();

#pragma unroll 1
    for (int t = 0; t < Tt; t++) {
        const int p = t & 1;
        float gxr = 0.f, gxz = 0.f, gxn = 0.f;
        if (q == 0) {
            const float* gxp = g_GX2 + ((size_t)b * Tt + t) * 384 + j;
            gxr = __ldcs(gxp);
            gxz = __ldcs(gxp + 128);
            gxn = __ldcs(gxp + 256);
        }
        const unsigned long long* hb =
            reinterpret_cast<const unsigned long long*>(&hsh[p][0]) + q * 32;
        unsigned long long ar = 0ull, az = 0ull, an = 0ull;
#pragma unroll
        for (int i = 0; i < 32; i++) {
            unsigned long long h2 = hb[i];
            ar = fma2_(wr[i], h2, ar);
            az = fma2_(wz[i], h2, az);
            an = fma2_(wn[i], h2, an);
        }
        float2 fr = unpack2_(ar), fz = unpack2_(az), fn = unpack2_(an);
        float dr = fr.x + fr.y, dz = fz.x + fz.y, dn = fn.x + fn.y;
        dr += __shfl_xor_sync(0xFFFFFFFFu, dr, 1);
        dz += __shfl_xor_sync(0xFFFFFFFFu, dz, 1);
        dn += __shfl_xor_sync(0xFFFFFFFFu, dn, 1);
        if (q == 0) {
            float r = sigm_(gxr + dr + br);
            float z = sigm_(gxz + dz + bz);
            float n = tanh_(gxn + r * (dn + bn_));
            float hnew = (1.f - z) * n + z * hsh[p][j];
            hsh[p ^ 1][j] = hnew;
            __stcs(&g_H2[((size_t)b * Tt + t) * 128 + j], hnew);
        }
        __syncthreads();
    }
}

// ---------------- epilogue: BN2 + max over T + tanh + FC -------------------
__global__ void __launch_bounds__(128)
final_kernel(const float* __restrict__ g2, const float* __restrict__ be2,
             const float* __restrict__ m2, const float* __restrict__ v2,
             const float* __restrict__ fcw, const float* __restrict__ fcb,
             float* __restrict__ out)
{
    __shared__ float tm[128];
    const int b = blockIdx.x, j = threadIdx.x;
    float s  = g2[j] * rsqrtf(v2[j] + EPSf);
    float tb = be2[j] - m2[j] * s;
    float mx = -3.402823466e38f;
    const float* p = g_H2 + (size_t)b * Tt * 128 + j;
#pragma unroll 8
    for (int t = 0; t < Tt; t++)
        mx = fmaxf(mx, p[(size_t)t * 128] * s + tb);
    tm[j] = tanh_(mx);
    __syncthreads();
    if (j < Oc) {
        float acc = fcb[j];
#pragma unroll 4
        for (int k = 0; k < 128; k++)
            acc = fmaf(tm[k], fcw[j * 128 + k], acc);
        out[b * Oc + j] = acc;
    }
}

// ---------------------------------------------------------------------------
extern "C" void kernel_launch(void* const* d_in, const int* in_sizes, int n_in,
                              void* d_out, int out_size)
{
    const float* x     = (const float*)d_in[0];
    const float* Wih1  = (const float*)d_in[1];
    const float* Whh1  = (const float*)d_in[2];
    const float* bih1  = (const float*)d_in[3];
    const float* bhh1  = (const float*)d_in[4];
    const float* bn1g  = (const float*)d_in[5];
    const float* bn1b  = (const float*)d_in[6];
    const float* bn1m  = (const float*)d_in[7];
    const float* bn1v  = (const float*)d_in[8];
    const float* Wih2  = (const float*)d_in[9];
    const float* Whh2  = (const float*)d_in[10];
    const float* bih2  = (const float*)d_in[11];
    const float* bhh2  = (const float*)d_in[12];
    const float* bn2g  = (const float*)d_in[13];
    const float* bn2b  = (const float*)d_in[14];
    const float* bn2m  = (const float*)d_in[15];
    const float* bn2v  = (const float*)d_in[16];
    const float* fcw   = (const float*)d_in[17];
    const float* fcb   = (const float*)d_in[18];
    float* out = (float*)d_out;

    static float *pGX1 = nullptr, *pGX2 = nullptr, *pH1 = nullptr;
    static float *pW2eff = nullptr, *pb2eff = nullptr;
    static bool inited = false;
    if (!inited) {
        cudaGetSymbolAddress((void**)&pGX1,   g_GX1);
        cudaGetSymbolAddress((void**)&pGX2,   g_GX2);
        cudaGetSymbolAddress((void**)&pH1,    g_H1);
        cudaGetSymbolAddress((void**)&pW2eff, g_W2eff);
        cudaGetSymbolAddress((void**)&pb2eff, g_b2eff);
        inited = true;
    }

    // 1) fold BN1 into layer-2 input weights
    prep_kernel<<<3 * H2c, 256>>>(Wih2, bih2, bn1g, bn1b, bn1m, bn1v);

    // 2) GX1 = x @ W_ih1^T + b_ih1   (M=131072, N=768, K=64)
    gemm_bias_kernel<<<dim3(768 / 64, (Bsz * Tt) / 128), 256>>>(
        x, Wih1, bih1, pGX1, 768, 64);

    // 3) GRU layer-1 recurrence (32 clusters x 4 CTAs, batch-staggered)
    gru1_kernel<<<128, 384>>>(Whh1, bhh1);

    // 4) GX2 = H1 @ W2eff^T + b2eff  (M=131072, N=384, K=256)
    gemm_bias_kernel<<<dim3(384 / 64, (Bsz * Tt) / 128), 256>>>(
        pH1, pW2eff, pb2eff, pGX2, 384, 256);

    // 5) GRU layer-2 recurrence (1 CTA / batch, inline combine)
    gru2_kernel<<<Bsz, 256>>>(Whh2, bhh2);

    // 6) BN2 + global max pool + tanh + FC
    final_kernel<<<Bsz, 128>>>(bn2g, bn2b, bn2m, bn2v, fcw, fcb, out);
}